// round 15
// baseline (speedup 1.0000x reference)
#include <cuda_runtime.h>
#include <cstdint>

// ---------------------------------------------------------------------------
// VMD on GB300, round 14:
//   - vmd_loop: lambda-free (R13) + HIGH OCCUPANCY: 1024 threads (32 warps/SM,
//     8/SMSP), EPT=8, 64-reg cap via launch_bounds. All state in registers
//     (m2p/fpk = 16 u64), so no LDS on the critical path (unlike R5).
//   - FFT: four-step 1024x1024 with precomputed twiddle tables.
// ---------------------------------------------------------------------------

#define T_N     (1 << 20)
#define T_MASK  (T_N - 1)
#define T_HALF  (1 << 19)

#define NBLK    128
#define NTHR    1024
#define EPT     8
#define NPAIR   (EPT / 2)
#define CHUNK   (NTHR * EPT)          // 8192 elems per block

#define ALPHA_C 2000.0f
#define TOL_C   1e-6f

// ---- FFT geometry: N = 1024 x 1024 ----
#define TA      8
#define FTHR    512
#define CSTR    1028
#define FBLK    128
#define F_SMEM  ((2 * TA * CSTR + 2 * 1024) * 8)

typedef unsigned long long u64;

// ------------------------- device global scratch ---------------------------
__device__ float2   g_bufA[3 * T_N];
__device__ float2   g_bufB[3 * T_N];
__device__ float2   g_tw1k[1024];     // e^{-2pi i j/1024}
__device__ float2   g_twfn[1024];     // e^{-2pi i j/2^20}
__device__ float    g_part[2 * NBLK * 8];
__device__ float    g_part2[NBLK * 2];
__device__ unsigned g_bar_cnt;
__device__ unsigned g_bar_epoch;

// --------------------------- f32x2 helpers ---------------------------------
__device__ __forceinline__ u64 f2pk(float lo, float hi) {
    u64 d; asm("mov.b64 %0,{%1,%2};" : "=l"(d) : "f"(lo), "f"(hi)); return d;
}
__device__ __forceinline__ void f2up(u64 v, float& lo, float& hi) {
    asm("mov.b64 {%0,%1},%2;" : "=f"(lo), "=f"(hi) : "l"(v));
}
__device__ __forceinline__ u64 f2spl(float x) { return f2pk(x, x); }
__device__ __forceinline__ u64 f2add(u64 a, u64 b) {
    u64 d; asm("add.rn.f32x2 %0,%1,%2;" : "=l"(d) : "l"(a), "l"(b)); return d;
}
__device__ __forceinline__ u64 f2mul(u64 a, u64 b) {
    u64 d; asm("mul.rn.f32x2 %0,%1,%2;" : "=l"(d) : "l"(a), "l"(b)); return d;
}
__device__ __forceinline__ u64 f2fma(u64 a, u64 b, u64 c) {
    u64 d; asm("fma.rn.f32x2 %0,%1,%2,%3;" : "=l"(d) : "l"(a), "l"(b), "l"(c)); return d;
}

// packed mode scales for an element pair: s_k = 1/(1+alpha*denom_k), one rcp.
__device__ __forceinline__ void msc2(u64 fp, u64 nw0, u64 nw1, u64 nw2,
                                     u64 CAL, u64 CONE,
                                     u64& s0, u64& s1, u64& s2) {
    u64 e0 = f2add(fp, nw0), e1 = f2add(fp, nw1), e2 = f2add(fp, nw2);
    u64 d0 = f2mul(e0, e0), d1 = f2mul(e1, e1), d2 = f2mul(e2, e2);
    u64 t01 = f2add(d0, d1), t12 = f2add(d1, d2);
    u64 t012 = f2add(t01, d2);
    u64 A0 = f2fma(CAL, t01, CONE);
    u64 A1 = f2fma(CAL, t012, CONE);
    u64 A2 = f2fma(CAL, t12, CONE);
    u64 p01 = f2mul(A0, A1), p12 = f2mul(A1, A2), p02 = f2mul(A0, A2);
    u64 p = f2mul(p01, A2);
    float pa, pb; f2up(p, pa, pb);
    float P = pa * pb, r;
    asm("rcp.approx.f32 %0,%1;" : "=f"(r) : "f"(P));
    r = r * fmaf(-P, r, 2.0f);
    u64 rp = f2pk(r * pb, r * pa);               // (1/pa, 1/pb)
    s0 = f2mul(rp, p12); s1 = f2mul(rp, p02); s2 = f2mul(rp, p01);
}

__device__ __forceinline__ float2 cmulf(float ux, float uy, float2 w) {
    return make_float2(fmaf(ux, w.x, -uy * w.y), fmaf(ux, w.y, uy * w.x));
}
__device__ __forceinline__ float2 cmul2(float2 a, float2 b) {
    return make_float2(fmaf(a.x, b.x, -a.y * b.y), fmaf(a.x, b.y, a.y * b.x));
}
__device__ __forceinline__ int swz(int m) {
    int h = (m >> 4) & 15;
    return m ^ (h ^ ((h << 1) & 15));
}

// Central sense-reversing grid barrier (R4-proven shape).
__device__ __forceinline__ void gbar(unsigned* ep) {
    __syncthreads();
    if (threadIdx.x == 0) {
        unsigned target = ++(*ep);
        unsigned prev = atomicAdd(&g_bar_cnt, 1u);
        if (prev == NBLK - 1) {
            g_bar_cnt = 0u;
            __threadfence();
            atomicExch(&g_bar_epoch, target);
        } else {
            while (*((volatile unsigned*)&g_bar_epoch) < target) { }
            __threadfence();
        }
    }
    __syncthreads();
}

// ------------------------------ kernels ------------------------------------
__global__ void tw_init() {
    int j = threadIdx.x;                       // 1024 threads
    float s, c;
    sincospif(-(float)j * (1.0f / 512.0f), &s, &c);
    g_tw1k[j] = make_float2(c, s);
    sincospif(-(float)j * (1.0f / 524288.0f), &s, &c);
    g_twfn[j] = make_float2(c, s);
    if (j == 0) { g_bar_cnt = 0u; g_bar_epoch = 0u; }
}

// 1024-pt smem FFT core: 5 radix-4 Stockham stages, ping<->pong.
__device__ __forceinline__ void fft1k_smem(float2* p0, float2* p1,
                                           const float2* s1k, int tid) {
#pragma unroll
    for (int p = 0; p < 5; p++) {
        const int s = 1 << (2 * p);
        float2* pin  = (p & 1) ? p1 : p0;
        float2* pout = (p & 1) ? p0 : p1;
#pragma unroll
        for (int jj = 0; jj < 4; jj++) {
            int w = tid + jj * FTHR;
            int col = w >> 8, t = w & 255;
            float2* cb = pin + col * CSTR;
            float2 a = cb[swz(t)];
            float2 b = cb[swz(t + 256)];
            float2 c = cb[swz(t + 512)];
            float2 d = cb[swz(t + 768)];
            int q = t & (s - 1);
            int ps = t - q;
            float2 w1 = s1k[ps], w2 = s1k[2 * ps], w3 = s1k[3 * ps];
            float apcx = a.x + c.x, apcy = a.y + c.y;
            float amcx = a.x - c.x, amcy = a.y - c.y;
            float bpdx = b.x + d.x, bpdy = b.y + d.y;
            float bmdx = b.x - d.x, bmdy = b.y - d.y;
            int ob = t + 3 * ps;
            float2* ob_ = pout + col * CSTR;
            ob_[swz(ob)]         = make_float2(apcx + bpdx, apcy + bpdy);
            ob_[swz(ob + s)]     = cmulf(amcx + bmdy, amcy - bmdx, w1);
            ob_[swz(ob + 2 * s)] = cmulf(apcx - bpdx, apcy - bpdy, w2);
            ob_[swz(ob + 3 * s)] = cmulf(amcx - bmdy, amcy + bmdx, w3);
        }
        __syncthreads();
    }
}

// Step 1: FFT over b (stride-1024) + inter twiddle e^{-2pi i ac/2^20}.
__global__ void __launch_bounds__(FTHR, 1) fft_s1(const float* __restrict__ xreal) {
    extern __shared__ float2 smemf[];
    float2* p0  = smemf;
    float2* p1  = p0 + TA * CSTR;
    float2* s1k = p1 + TA * CSTR;
    float2* sfn = s1k + 1024;
    const int tid = threadIdx.x;
    const int a0  = blockIdx.x * TA;
    const long boff = (long)blockIdx.y * T_N;

#pragma unroll
    for (int i = tid; i < 1024; i += FTHR) {
        s1k[i] = g_tw1k[i];
        sfn[i] = g_twfn[i];
    }

    if (xreal) {
#pragma unroll
        for (int jj = 0; jj < 16; jj++) {
            int e = tid + jj * FTHR;
            int al = e & 7, b = e >> 3;
            p0[al * CSTR + swz(b)] = make_float2(xreal[a0 + al + (b << 10)], 0.0f);
        }
    } else {
        const float2* __restrict__ src = g_bufB + boff;
#pragma unroll
        for (int jj = 0; jj < 16; jj++) {
            int e = tid + jj * FTHR;
            int al = e & 7, b = e >> 3;
            p0[al * CSTR + swz(b)] = src[a0 + al + (b << 10)];
        }
    }
    __syncthreads();

    fft1k_smem(p0, p1, s1k, tid);

    float2* dst = xreal ? g_bufB : (g_bufA + boff);
#pragma unroll
    for (int jj = 0; jj < 16; jj++) {
        int e = tid + jj * FTHR;
        int al = e & 7, c = e >> 3;
        int a = a0 + al;
        float2 y = p1[al * CSTR + swz(c)];
        int prod = a * c;
        float2 w = cmul2(s1k[prod >> 10], sfn[prod & 1023]);
        dst[(c << 10) + a] = cmul2(y, w);
    }
}

// Step 2: FFT over a (contiguous), transposed write.
__global__ void __launch_bounds__(FTHR, 1) fft_s2(int mode, float* __restrict__ outp) {
    extern __shared__ float2 smemf[];
    float2* p0  = smemf;
    float2* p1  = p0 + TA * CSTR;
    float2* s1k = p1 + TA * CSTR;
    const int tid = threadIdx.x;
    const int c0  = blockIdx.x * TA;
    const long boff = (long)blockIdx.y * T_N;

#pragma unroll
    for (int i = tid; i < 1024; i += FTHR) s1k[i] = g_tw1k[i];

    const float2* __restrict__ src = (mode ? g_bufA : g_bufB) + boff;
#pragma unroll
    for (int jj = 0; jj < 16; jj++) {
        int e = tid + jj * FTHR;
        int r = e >> 10, a = e & 1023;
        p0[r * CSTR + swz(a)] = src[(long)c0 * 1024 + e];
    }
    __syncthreads();

    fft1k_smem(p0, p1, s1k, tid);

    if (mode == 0) {
        float2* dst = g_bufA + boff;
#pragma unroll
        for (int jj = 0; jj < 16; jj++) {
            int e = tid + jj * FTHR;
            int cl = e & 7, d = e >> 3;
            dst[(d << 10) + c0 + cl] = p1[cl * CSTR + swz(d)];
        }
    } else {
        float* dst = outp + boff;
        const float invT = 1.0f / (float)T_N;
#pragma unroll
        for (int jj = 0; jj < 16; jj++) {
            int e = tid + jj * FTHR;
            int cl = e & 7, d = e >> 3;
            dst[(d << 10) + c0 + cl] = p1[cl * CSTR + swz(d)].x * invT;
        }
    }
}

// ------------------- persistent VMD loop (lambda-free, hi-occ) -------------
__global__ void __launch_bounds__(NTHR, 1) vmd_loop(const float* __restrict__ om_init) {
    __shared__ float red[32 * 8];
    __shared__ float red2[8];

    const int tid  = threadIdx.x;
    const int blk  = blockIdx.x;
    const int base = blk * CHUNK + tid;
    const float invT = 1.0f / (float)T_N;
    const float fstep = (float)NTHR * invT;
    const float fbase = (float)base * invT - 0.5f;

    const u64 CAL  = f2spl(ALPHA_C);
    const u64 CONE = f2spl(1.0f);
    const u64 CM1  = f2spl(-1.0f);

    // Precompute packed weights m2 = |f_hat|^2 and packed freqs per pair.
    u64 m2p[NPAIR];
    u64 fpk[NPAIR];
#pragma unroll
    for (int jp = 0; jp < NPAIR; jp++) {
        const int j0 = 2 * jp, j1 = j0 + 1;
        float2 v0 = g_bufA[((base + j0 * NTHR) + T_HALF) & T_MASK];
        float2 v1 = g_bufA[((base + j1 * NTHR) + T_HALF) & T_MASK];
        m2p[jp] = f2pk(fmaf(v0.x, v0.x, v0.y * v0.y),
                       fmaf(v1.x, v1.x, v1.y * v1.y));
        float fa = fbase + (float)j0 * fstep;
        fpk[jp] = f2pk(fa, fa + fstep);
    }

    float om0 = om_init[0], om1 = om_init[1], om2 = om_init[2];
    float op0 = om0, op1 = om1, op2 = om2;
    float fo0 = om0, fo1 = om1, fo2 = om2;
    unsigned epoch = 0;
    bool fin = false;
    const unsigned wid = tid >> 5, lane = tid & 31;

    for (int n = 0; n < 49 && !fin; n++) {
        const bool chk = (n > 0) && (n % 10 == 0);
        const int  par = n & 1;

        const u64 nw0 = f2spl(-om0), nw1 = f2spl(-om1), nw2 = f2spl(-om2);

        u64 af0 = 0, af1 = 0, af2 = 0, ap0 = 0, ap1 = 0, ap2 = 0;

        // ---- HOT pass: omega sums only (registers only) ----
#pragma unroll
        for (int jp = 0; jp < NPAIR; jp++) {
            u64 s0, s1, s2;
            msc2(fpk[jp], nw0, nw1, nw2, CAL, CONE, s0, s1, s2);
            u64 q0 = f2mul(f2mul(s0, s0), m2p[jp]);
            u64 q1 = f2mul(f2mul(s1, s1), m2p[jp]);
            u64 q2 = f2mul(f2mul(s2, s2), m2p[jp]);
            af0 = f2fma(fpk[jp], q0, af0); ap0 = f2add(ap0, q0);
            af1 = f2fma(fpk[jp], q1, af1); ap1 = f2add(ap1, q1);
            af2 = f2fma(fpk[jp], q2, af2); ap2 = f2add(ap2, q2);
        }

        // ---- stage 1: per-warp shuffle reduce of 6 scalars ----
        float hv[6];
        { float a, b;
          f2up(af0, a, b); hv[0] = a + b;  f2up(af1, a, b); hv[1] = a + b;
          f2up(af2, a, b); hv[2] = a + b;  f2up(ap0, a, b); hv[3] = a + b;
          f2up(ap1, a, b); hv[4] = a + b;  f2up(ap2, a, b); hv[5] = a + b; }
#pragma unroll
        for (int k = 0; k < 6; k++) {
            float v = hv[k];
#pragma unroll
            for (int o = 16; o > 0; o >>= 1) v += __shfl_down_sync(0xffffffffu, v, o);
            if (lane == 0) red[wid * 8 + k] = v;
        }
        __syncthreads();

        // ---- stage 2: warp k (k<6) reduces 32 warp-partials; publish ----
        if (wid < 6) {
            float v = red[lane * 8 + wid];
#pragma unroll
            for (int o = 16; o > 0; o >>= 1) v += __shfl_down_sync(0xffffffffu, v, o);
            if (lane == 0) {
                g_part[par * NBLK * 8 + blk * 8 + wid] = v;
                __threadfence();
            }
        }

        gbar(&epoch);

        // ---- stage 3: warp k (k<6) sums 128 block-partials of acc k ----
        if (wid < 6) {
            const float* pp = g_part + par * NBLK * 8 + wid;
            float v = __ldcg(pp + lane * 8) + __ldcg(pp + (lane + 32) * 8)
                    + __ldcg(pp + (lane + 64) * 8) + __ldcg(pp + (lane + 96) * 8);
#pragma unroll
            for (int o = 16; o > 0; o >>= 1) v += __shfl_down_sync(0xffffffffu, v, o);
            if (lane == 0) red2[wid] = v;
        }
        __syncthreads();

        float wn0 = red2[0] / red2[3];
        float wn1 = red2[1] / red2[4];
        float wn2 = red2[2] / red2[5];
        __syncthreads();

        bool brk = false;
        if (chk) {
            float od = (fabsf(wn0 - wn2) + fabsf(wn1 - wn0) + fabsf(wn2 - wn1)) * (1.0f / 3.0f);
            if (od < TOL_C) {
                // ==== RARE deferred u_diff pass (uniform decision) ====
                const u64 no0 = f2spl(-op0), no1 = f2spl(-op1), no2 = f2spl(-op2);
                u64 a6 = 0, a7 = 0;
#pragma unroll
                for (int jp = 0; jp < NPAIR; jp++) {
                    u64 s0, s1, s2, t0, t1, t2;
                    msc2(fpk[jp], nw0, nw1, nw2, CAL, CONE, s0, s1, s2);
                    msc2(fpk[jp], no0, no1, no2, CAL, CONE, t0, t1, t2);
                    u64 d0 = f2fma(t0, CM1, s0);
                    u64 d1 = f2fma(t1, CM1, s1);
                    u64 d2 = f2fma(t2, CM1, s2);
                    u64 dd = f2fma(d0, d0, f2fma(d1, d1, f2mul(d2, d2)));
                    a6 = f2fma(m2p[jp], dd, a6);
                    u64 tt = f2fma(t0, t0, f2fma(t1, t1, f2mul(t2, t2)));
                    a7 = f2fma(m2p[jp], tt, a7);
                }
                float h6, h7;
                { float a, b;
                  f2up(a6, a, b); h6 = a + b;
                  f2up(a7, a, b); h7 = a + b; }
#pragma unroll
                for (int o = 16; o > 0; o >>= 1) {
                    h6 += __shfl_down_sync(0xffffffffu, h6, o);
                    h7 += __shfl_down_sync(0xffffffffu, h7, o);
                }
                if (lane == 0) { red[wid * 2] = h6; red[wid * 2 + 1] = h7; }
                __syncthreads();
                if (wid < 2) {
                    float v = red[lane * 2 + wid];
#pragma unroll
                    for (int o = 16; o > 0; o >>= 1) v += __shfl_down_sync(0xffffffffu, v, o);
                    if (lane == 0) {
                        g_part2[blk * 2 + wid] = v;
                        __threadfence();
                    }
                }
                gbar(&epoch);
                if (wid < 2) {
                    const float* pp = g_part2 + wid;
                    float v = __ldcg(pp + lane * 2) + __ldcg(pp + (lane + 32) * 2)
                            + __ldcg(pp + (lane + 64) * 2) + __ldcg(pp + (lane + 96) * 2);
#pragma unroll
                    for (int o = 16; o > 0; o >>= 1) v += __shfl_down_sync(0xffffffffu, v, o);
                    if (lane == 0) red2[wid] = v;
                }
                __syncthreads();
                float ud = red2[0] / red2[1];
                brk = (ud < TOL_C);
                __syncthreads();
            }
        }

        if (brk) {
            fin = true;
            fo0 = om0; fo1 = om1; fo2 = om2;   // omega entering the break iter
        } else {
            op0 = om0; op1 = om1; op2 = om2;
            om0 = wn0; om1 = wn1; om2 = wn2;
        }
    }
    if (!fin) { fo0 = om0; fo1 = om1; fo2 = om2; }   // omega^(49)

    // ---- final u_hat = f_hat * s_k(omega_final): conj(ifftshift) to bufB --
    const u64 nf0 = f2spl(-fo0), nf1 = f2spl(-fo1), nf2 = f2spl(-fo2);
#pragma unroll
    for (int jp = 0; jp < NPAIR; jp++) {
        const int j0 = 2 * jp, j1 = j0 + 1;
        u64 s0, s1, s2;
        msc2(fpk[jp], nf0, nf1, nf2, CAL, CONE, s0, s1, s2);
        float s0a, s0b, s1a, s1b, s2a, s2b;
        f2up(s0, s0a, s0b); f2up(s1, s1a, s1b); f2up(s2, s2a, s2b);

        int jd = ((base + j0 * NTHR) + T_HALF) & T_MASK;
        float2 v = g_bufA[jd];
        g_bufB[jd]           = make_float2(v.x * s0a, -(v.y * s0a));
        g_bufB[T_N + jd]     = make_float2(v.x * s1a, -(v.y * s1a));
        g_bufB[2 * T_N + jd] = make_float2(v.x * s2a, -(v.y * s2a));

        jd = ((base + j1 * NTHR) + T_HALF) & T_MASK;
        v = g_bufA[jd];
        g_bufB[jd]           = make_float2(v.x * s0b, -(v.y * s0b));
        g_bufB[T_N + jd]     = make_float2(v.x * s1b, -(v.y * s1b));
        g_bufB[2 * T_N + jd] = make_float2(v.x * s2b, -(v.y * s2b));
    }
}

// ------------------------------ launcher -----------------------------------
extern "C" void kernel_launch(void* const* d_in, const int* in_sizes, int n_in,
                              void* d_out, int out_size) {
    (void)in_sizes; (void)n_in; (void)out_size;
    const float* x  = (const float*)d_in[0];
    const float* om = (const float*)d_in[1];
    float* out = (float*)d_out;

    cudaFuncSetAttribute((const void*)fft_s1,
                         cudaFuncAttributeMaxDynamicSharedMemorySize, F_SMEM);
    cudaFuncSetAttribute((const void*)fft_s2,
                         cudaFuncAttributeMaxDynamicSharedMemorySize, F_SMEM);

    // Twiddle tables + barrier-state reset (once per launch).
    tw_init<<<1, 1024>>>();

    // FFT(x): x -> bufB (S1), bufB -> bufA (S2)
    fft_s1<<<dim3(FBLK, 1), FTHR, F_SMEM>>>(x);
    fft_s2<<<dim3(FBLK, 1), FTHR, F_SMEM>>>(0, nullptr);

    // 49 lambda-free VMD iterations; writes conj(ifftshift(u_hat)) to bufB.
    vmd_loop<<<NBLK, NTHR>>>(om);

    // FFT of the 3 modes: bufB -> bufA (S1), bufA -> out real (S2)
    fft_s1<<<dim3(FBLK, 3), FTHR, F_SMEM>>>(nullptr);
    fft_s2<<<dim3(FBLK, 3), FTHR, F_SMEM>>>(1, out);
}

// round 16
// speedup vs baseline: 1.0633x; 1.0633x over previous
#include <cuda_runtime.h>
#include <cstdint>

// ---------------------------------------------------------------------------
// VMD on GB300, round 15:
//   - vmd_loop: R13 champion structure (512 thr, NPAIR=8, lambda-free) with
//     register-pressure relief: fpk recomputed per pair (16 regs freed) and
//     q_k = p_jk^2 * (rp^2 * m2) so s_k never materializes in the hot path.
//   - FFT: four-step 1024x1024 with precomputed twiddle tables.
// ---------------------------------------------------------------------------

#define T_N     (1 << 20)
#define T_MASK  (T_N - 1)
#define T_HALF  (1 << 19)

#define NBLK    128
#define NTHR    512
#define EPT     16
#define NPAIR   (EPT / 2)
#define CHUNK   (NTHR * EPT)          // 8192 elems per block

#define ALPHA_C 2000.0f
#define TOL_C   1e-6f

// ---- FFT geometry: N = 1024 x 1024 ----
#define TA      8
#define FTHR    512
#define CSTR    1028
#define FBLK    128
#define F_SMEM  ((2 * TA * CSTR + 2 * 1024) * 8)

typedef unsigned long long u64;

// ------------------------- device global scratch ---------------------------
__device__ float2   g_bufA[3 * T_N];
__device__ float2   g_bufB[3 * T_N];
__device__ float2   g_tw1k[1024];     // e^{-2pi i j/1024}
__device__ float2   g_twfn[1024];     // e^{-2pi i j/2^20}
__device__ float    g_part[2 * NBLK * 8];
__device__ float    g_part2[NBLK * 2];
__device__ unsigned g_bar_cnt;
__device__ unsigned g_bar_epoch;

// --------------------------- f32x2 helpers ---------------------------------
__device__ __forceinline__ u64 f2pk(float lo, float hi) {
    u64 d; asm("mov.b64 %0,{%1,%2};" : "=l"(d) : "f"(lo), "f"(hi)); return d;
}
__device__ __forceinline__ void f2up(u64 v, float& lo, float& hi) {
    asm("mov.b64 {%0,%1},%2;" : "=f"(lo), "=f"(hi) : "l"(v));
}
__device__ __forceinline__ u64 f2spl(float x) { return f2pk(x, x); }
__device__ __forceinline__ u64 f2add(u64 a, u64 b) {
    u64 d; asm("add.rn.f32x2 %0,%1,%2;" : "=l"(d) : "l"(a), "l"(b)); return d;
}
__device__ __forceinline__ u64 f2mul(u64 a, u64 b) {
    u64 d; asm("mul.rn.f32x2 %0,%1,%2;" : "=l"(d) : "l"(a), "l"(b)); return d;
}
__device__ __forceinline__ u64 f2fma(u64 a, u64 b, u64 c) {
    u64 d; asm("fma.rn.f32x2 %0,%1,%2,%3;" : "=l"(d) : "l"(a), "l"(b), "l"(c)); return d;
}

// Partial mode-scale computation for an element pair: returns the packed
// reciprocal rp = (1/(A0A1A2)_a, 1/(A0A1A2)_b) and the pair products
// p01=A0A1, p12=A1A2, p02=A0A2.  s_k = rp*p_{jk}; q_k = p_{jk}^2 * rp^2 * m2.
__device__ __forceinline__ void mscp(u64 fp, u64 nw0, u64 nw1, u64 nw2,
                                     u64 CAL, u64 CONE,
                                     u64& p01, u64& p12, u64& p02, u64& rp) {
    u64 e0 = f2add(fp, nw0), e1 = f2add(fp, nw1), e2 = f2add(fp, nw2);
    u64 d0 = f2mul(e0, e0), d1 = f2mul(e1, e1), d2 = f2mul(e2, e2);
    u64 t01 = f2add(d0, d1), t12 = f2add(d1, d2);
    u64 t012 = f2add(t01, d2);
    u64 A0 = f2fma(CAL, t01, CONE);
    u64 A1 = f2fma(CAL, t012, CONE);
    u64 A2 = f2fma(CAL, t12, CONE);
    p01 = f2mul(A0, A1); p12 = f2mul(A1, A2); p02 = f2mul(A0, A2);
    u64 p = f2mul(p01, A2);
    float pa, pb; f2up(p, pa, pb);
    float P = pa * pb, r;
    asm("rcp.approx.f32 %0,%1;" : "=f"(r) : "f"(P));
    r = r * fmaf(-P, r, 2.0f);
    rp = f2pk(r * pb, r * pa);                   // (1/pa, 1/pb)
}

// Full scales (used only off the hot path).
__device__ __forceinline__ void msc2(u64 fp, u64 nw0, u64 nw1, u64 nw2,
                                     u64 CAL, u64 CONE,
                                     u64& s0, u64& s1, u64& s2) {
    u64 p01, p12, p02, rp;
    mscp(fp, nw0, nw1, nw2, CAL, CONE, p01, p12, p02, rp);
    s0 = f2mul(rp, p12); s1 = f2mul(rp, p02); s2 = f2mul(rp, p01);
}

__device__ __forceinline__ float2 cmulf(float ux, float uy, float2 w) {
    return make_float2(fmaf(ux, w.x, -uy * w.y), fmaf(ux, w.y, uy * w.x));
}
__device__ __forceinline__ float2 cmul2(float2 a, float2 b) {
    return make_float2(fmaf(a.x, b.x, -a.y * b.y), fmaf(a.x, b.y, a.y * b.x));
}
__device__ __forceinline__ int swz(int m) {
    int h = (m >> 4) & 15;
    return m ^ (h ^ ((h << 1) & 15));
}

// Central sense-reversing grid barrier (R4-proven shape).
__device__ __forceinline__ void gbar(unsigned* ep) {
    __syncthreads();
    if (threadIdx.x == 0) {
        unsigned target = ++(*ep);
        unsigned prev = atomicAdd(&g_bar_cnt, 1u);
        if (prev == NBLK - 1) {
            g_bar_cnt = 0u;
            __threadfence();
            atomicExch(&g_bar_epoch, target);
        } else {
            while (*((volatile unsigned*)&g_bar_epoch) < target) { }
            __threadfence();
        }
    }
    __syncthreads();
}

// ------------------------------ kernels ------------------------------------
__global__ void tw_init() {
    int j = threadIdx.x;                       // 1024 threads
    float s, c;
    sincospif(-(float)j * (1.0f / 512.0f), &s, &c);
    g_tw1k[j] = make_float2(c, s);
    sincospif(-(float)j * (1.0f / 524288.0f), &s, &c);
    g_twfn[j] = make_float2(c, s);
    if (j == 0) { g_bar_cnt = 0u; g_bar_epoch = 0u; }
}

// 1024-pt smem FFT core: 5 radix-4 Stockham stages, ping<->pong.
__device__ __forceinline__ void fft1k_smem(float2* p0, float2* p1,
                                           const float2* s1k, int tid) {
#pragma unroll
    for (int p = 0; p < 5; p++) {
        const int s = 1 << (2 * p);
        float2* pin  = (p & 1) ? p1 : p0;
        float2* pout = (p & 1) ? p0 : p1;
#pragma unroll
        for (int jj = 0; jj < 4; jj++) {
            int w = tid + jj * FTHR;
            int col = w >> 8, t = w & 255;
            float2* cb = pin + col * CSTR;
            float2 a = cb[swz(t)];
            float2 b = cb[swz(t + 256)];
            float2 c = cb[swz(t + 512)];
            float2 d = cb[swz(t + 768)];
            int q = t & (s - 1);
            int ps = t - q;
            float2 w1 = s1k[ps], w2 = s1k[2 * ps], w3 = s1k[3 * ps];
            float apcx = a.x + c.x, apcy = a.y + c.y;
            float amcx = a.x - c.x, amcy = a.y - c.y;
            float bpdx = b.x + d.x, bpdy = b.y + d.y;
            float bmdx = b.x - d.x, bmdy = b.y - d.y;
            int ob = t + 3 * ps;
            float2* ob_ = pout + col * CSTR;
            ob_[swz(ob)]         = make_float2(apcx + bpdx, apcy + bpdy);
            ob_[swz(ob + s)]     = cmulf(amcx + bmdy, amcy - bmdx, w1);
            ob_[swz(ob + 2 * s)] = cmulf(apcx - bpdx, apcy - bpdy, w2);
            ob_[swz(ob + 3 * s)] = cmulf(amcx - bmdy, amcy + bmdx, w3);
        }
        __syncthreads();
    }
}

// Step 1: FFT over b (stride-1024) + inter twiddle e^{-2pi i ac/2^20}.
__global__ void __launch_bounds__(FTHR, 1) fft_s1(const float* __restrict__ xreal) {
    extern __shared__ float2 smemf[];
    float2* p0  = smemf;
    float2* p1  = p0 + TA * CSTR;
    float2* s1k = p1 + TA * CSTR;
    float2* sfn = s1k + 1024;
    const int tid = threadIdx.x;
    const int a0  = blockIdx.x * TA;
    const long boff = (long)blockIdx.y * T_N;

#pragma unroll
    for (int i = tid; i < 1024; i += FTHR) {
        s1k[i] = g_tw1k[i];
        sfn[i] = g_twfn[i];
    }

    if (xreal) {
#pragma unroll
        for (int jj = 0; jj < 16; jj++) {
            int e = tid + jj * FTHR;
            int al = e & 7, b = e >> 3;
            p0[al * CSTR + swz(b)] = make_float2(xreal[a0 + al + (b << 10)], 0.0f);
        }
    } else {
        const float2* __restrict__ src = g_bufB + boff;
#pragma unroll
        for (int jj = 0; jj < 16; jj++) {
            int e = tid + jj * FTHR;
            int al = e & 7, b = e >> 3;
            p0[al * CSTR + swz(b)] = src[a0 + al + (b << 10)];
        }
    }
    __syncthreads();

    fft1k_smem(p0, p1, s1k, tid);

    float2* dst = xreal ? g_bufB : (g_bufA + boff);
#pragma unroll
    for (int jj = 0; jj < 16; jj++) {
        int e = tid + jj * FTHR;
        int al = e & 7, c = e >> 3;
        int a = a0 + al;
        float2 y = p1[al * CSTR + swz(c)];
        int prod = a * c;
        float2 w = cmul2(s1k[prod >> 10], sfn[prod & 1023]);
        dst[(c << 10) + a] = cmul2(y, w);
    }
}

// Step 2: FFT over a (contiguous), transposed write.
__global__ void __launch_bounds__(FTHR, 1) fft_s2(int mode, float* __restrict__ outp) {
    extern __shared__ float2 smemf[];
    float2* p0  = smemf;
    float2* p1  = p0 + TA * CSTR;
    float2* s1k = p1 + TA * CSTR;
    const int tid = threadIdx.x;
    const int c0  = blockIdx.x * TA;
    const long boff = (long)blockIdx.y * T_N;

#pragma unroll
    for (int i = tid; i < 1024; i += FTHR) s1k[i] = g_tw1k[i];

    const float2* __restrict__ src = (mode ? g_bufA : g_bufB) + boff;
#pragma unroll
    for (int jj = 0; jj < 16; jj++) {
        int e = tid + jj * FTHR;
        int r = e >> 10, a = e & 1023;
        p0[r * CSTR + swz(a)] = src[(long)c0 * 1024 + e];
    }
    __syncthreads();

    fft1k_smem(p0, p1, s1k, tid);

    if (mode == 0) {
        float2* dst = g_bufA + boff;
#pragma unroll
        for (int jj = 0; jj < 16; jj++) {
            int e = tid + jj * FTHR;
            int cl = e & 7, d = e >> 3;
            dst[(d << 10) + c0 + cl] = p1[cl * CSTR + swz(d)];
        }
    } else {
        float* dst = outp + boff;
        const float invT = 1.0f / (float)T_N;
#pragma unroll
        for (int jj = 0; jj < 16; jj++) {
            int e = tid + jj * FTHR;
            int cl = e & 7, d = e >> 3;
            dst[(d << 10) + c0 + cl] = p1[cl * CSTR + swz(d)].x * invT;
        }
    }
}

// ------------------- persistent VMD loop (lambda-free) ---------------------
__global__ void __launch_bounds__(NTHR, 1) vmd_loop(const float* __restrict__ om_init) {
    __shared__ float red[16 * 8];
    __shared__ float red2[8];

    const int tid  = threadIdx.x;
    const int blk  = blockIdx.x;
    const int base = blk * CHUNK + tid;
    const float invT = 1.0f / (float)T_N;
    const float fstep = (float)NTHR * invT;
    const float fbase = (float)base * invT - 0.5f;

    const u64 CAL  = f2spl(ALPHA_C);
    const u64 CONE = f2spl(1.0f);
    const u64 CM1  = f2spl(-1.0f);

    // Precompute packed weights m2 = |f_hat|^2 per pair (fpk recomputed).
    u64 m2p[NPAIR];
#pragma unroll
    for (int jp = 0; jp < NPAIR; jp++) {
        const int j0 = 2 * jp, j1 = j0 + 1;
        float2 v0 = g_bufA[((base + j0 * NTHR) + T_HALF) & T_MASK];
        float2 v1 = g_bufA[((base + j1 * NTHR) + T_HALF) & T_MASK];
        m2p[jp] = f2pk(fmaf(v0.x, v0.x, v0.y * v0.y),
                       fmaf(v1.x, v1.x, v1.y * v1.y));
    }

    float om0 = om_init[0], om1 = om_init[1], om2 = om_init[2];
    float op0 = om0, op1 = om1, op2 = om2;
    float fo0 = om0, fo1 = om1, fo2 = om2;
    unsigned epoch = 0;
    bool fin = false;
    const unsigned wid = tid >> 5, lane = tid & 31;

    for (int n = 0; n < 49 && !fin; n++) {
        const bool chk = (n > 0) && (n % 10 == 0);
        const int  par = n & 1;

        const u64 nw0 = f2spl(-om0), nw1 = f2spl(-om1), nw2 = f2spl(-om2);

        u64 af0 = 0, af1 = 0, af2 = 0, ap0 = 0, ap1 = 0, ap2 = 0;

        // ---- HOT pass: omega sums only (registers only) ----
#pragma unroll
        for (int jp = 0; jp < NPAIR; jp++) {
            float fa = fbase + (float)(2 * jp) * fstep;
            u64 fp = f2pk(fa, fa + fstep);
            u64 p01, p12, p02, rp;
            mscp(fp, nw0, nw1, nw2, CAL, CONE, p01, p12, p02, rp);
            u64 R2m = f2mul(f2mul(rp, rp), m2p[jp]);
            u64 q0 = f2mul(f2mul(p12, p12), R2m);
            u64 q1 = f2mul(f2mul(p02, p02), R2m);
            u64 q2 = f2mul(f2mul(p01, p01), R2m);
            af0 = f2fma(fp, q0, af0); ap0 = f2add(ap0, q0);
            af1 = f2fma(fp, q1, af1); ap1 = f2add(ap1, q1);
            af2 = f2fma(fp, q2, af2); ap2 = f2add(ap2, q2);
        }

        // ---- stage 1: per-warp shuffle reduce of 6 scalars ----
        float hv[6];
        { float a, b;
          f2up(af0, a, b); hv[0] = a + b;  f2up(af1, a, b); hv[1] = a + b;
          f2up(af2, a, b); hv[2] = a + b;  f2up(ap0, a, b); hv[3] = a + b;
          f2up(ap1, a, b); hv[4] = a + b;  f2up(ap2, a, b); hv[5] = a + b; }
#pragma unroll
        for (int k = 0; k < 6; k++) {
            float v = hv[k];
#pragma unroll
            for (int o = 16; o > 0; o >>= 1) v += __shfl_down_sync(0xffffffffu, v, o);
            if (lane == 0) red[wid * 8 + k] = v;
        }
        __syncthreads();

        // ---- stage 2: warp k (k<6) reduces 16 warp-partials; publish ----
        if (wid < 6) {
            float v = (lane < 16) ? red[lane * 8 + wid] : 0.0f;
#pragma unroll
            for (int o = 16; o > 0; o >>= 1) v += __shfl_down_sync(0xffffffffu, v, o);
            if (lane == 0) {
                g_part[par * NBLK * 8 + blk * 8 + wid] = v;
                __threadfence();
            }
        }

        gbar(&epoch);

        // ---- stage 3: warp k (k<6) sums 128 block-partials of acc k ----
        if (wid < 6) {
            const float* pp = g_part + par * NBLK * 8 + wid;
            float v = __ldcg(pp + lane * 8) + __ldcg(pp + (lane + 32) * 8)
                    + __ldcg(pp + (lane + 64) * 8) + __ldcg(pp + (lane + 96) * 8);
#pragma unroll
            for (int o = 16; o > 0; o >>= 1) v += __shfl_down_sync(0xffffffffu, v, o);
            if (lane == 0) red2[wid] = v;
        }
        __syncthreads();

        float wn0 = red2[0] / red2[3];
        float wn1 = red2[1] / red2[4];
        float wn2 = red2[2] / red2[5];
        __syncthreads();

        bool brk = false;
        if (chk) {
            float od = (fabsf(wn0 - wn2) + fabsf(wn1 - wn0) + fabsf(wn2 - wn1)) * (1.0f / 3.0f);
            if (od < TOL_C) {
                // ==== RARE deferred u_diff pass (uniform decision) ====
                const u64 no0 = f2spl(-op0), no1 = f2spl(-op1), no2 = f2spl(-op2);
                u64 a6 = 0, a7 = 0;
#pragma unroll
                for (int jp = 0; jp < NPAIR; jp++) {
                    float fa = fbase + (float)(2 * jp) * fstep;
                    u64 fp = f2pk(fa, fa + fstep);
                    u64 s0, s1, s2, t0, t1, t2;
                    msc2(fp, nw0, nw1, nw2, CAL, CONE, s0, s1, s2);
                    msc2(fp, no0, no1, no2, CAL, CONE, t0, t1, t2);
                    u64 d0 = f2fma(t0, CM1, s0);
                    u64 d1 = f2fma(t1, CM1, s1);
                    u64 d2 = f2fma(t2, CM1, s2);
                    u64 dd = f2fma(d0, d0, f2fma(d1, d1, f2mul(d2, d2)));
                    a6 = f2fma(m2p[jp], dd, a6);
                    u64 tt = f2fma(t0, t0, f2fma(t1, t1, f2mul(t2, t2)));
                    a7 = f2fma(m2p[jp], tt, a7);
                }
                float h6, h7;
                { float a, b;
                  f2up(a6, a, b); h6 = a + b;
                  f2up(a7, a, b); h7 = a + b; }
#pragma unroll
                for (int o = 16; o > 0; o >>= 1) {
                    h6 += __shfl_down_sync(0xffffffffu, h6, o);
                    h7 += __shfl_down_sync(0xffffffffu, h7, o);
                }
                if (lane == 0) { red[wid * 2] = h6; red[wid * 2 + 1] = h7; }
                __syncthreads();
                if (wid < 2) {
                    float v = (lane < 16) ? red[lane * 2 + wid] : 0.0f;
#pragma unroll
                    for (int o = 16; o > 0; o >>= 1) v += __shfl_down_sync(0xffffffffu, v, o);
                    if (lane == 0) {
                        g_part2[blk * 2 + wid] = v;
                        __threadfence();
                    }
                }
                gbar(&epoch);
                if (wid < 2) {
                    const float* pp = g_part2 + wid;
                    float v = __ldcg(pp + lane * 2) + __ldcg(pp + (lane + 32) * 2)
                            + __ldcg(pp + (lane + 64) * 2) + __ldcg(pp + (lane + 96) * 2);
#pragma unroll
                    for (int o = 16; o > 0; o >>= 1) v += __shfl_down_sync(0xffffffffu, v, o);
                    if (lane == 0) red2[wid] = v;
                }
                __syncthreads();
                float ud = red2[0] / red2[1];
                brk = (ud < TOL_C);
                __syncthreads();
            }
        }

        if (brk) {
            fin = true;
            fo0 = om0; fo1 = om1; fo2 = om2;   // omega entering the break iter
        } else {
            op0 = om0; op1 = om1; op2 = om2;
            om0 = wn0; om1 = wn1; om2 = wn2;
        }
    }
    if (!fin) { fo0 = om0; fo1 = om1; fo2 = om2; }   // omega^(49)

    // ---- final u_hat = f_hat * s_k(omega_final): conj(ifftshift) to bufB --
    const u64 nf0 = f2spl(-fo0), nf1 = f2spl(-fo1), nf2 = f2spl(-fo2);
#pragma unroll
    for (int jp = 0; jp < NPAIR; jp++) {
        const int j0 = 2 * jp, j1 = j0 + 1;
        float fa = fbase + (float)j0 * fstep;
        u64 fp = f2pk(fa, fa + fstep);
        u64 s0, s1, s2;
        msc2(fp, nf0, nf1, nf2, CAL, CONE, s0, s1, s2);
        float s0a, s0b, s1a, s1b, s2a, s2b;
        f2up(s0, s0a, s0b); f2up(s1, s1a, s1b); f2up(s2, s2a, s2b);

        int jd = ((base + j0 * NTHR) + T_HALF) & T_MASK;
        float2 v = g_bufA[jd];
        g_bufB[jd]           = make_float2(v.x * s0a, -(v.y * s0a));
        g_bufB[T_N + jd]     = make_float2(v.x * s1a, -(v.y * s1a));
        g_bufB[2 * T_N + jd] = make_float2(v.x * s2a, -(v.y * s2a));

        jd = ((base + j1 * NTHR) + T_HALF) & T_MASK;
        v = g_bufA[jd];
        g_bufB[jd]           = make_float2(v.x * s0b, -(v.y * s0b));
        g_bufB[T_N + jd]     = make_float2(v.x * s1b, -(v.y * s1b));
        g_bufB[2 * T_N + jd] = make_float2(v.x * s2b, -(v.y * s2b));
    }
}

// ------------------------------ launcher -----------------------------------
extern "C" void kernel_launch(void* const* d_in, const int* in_sizes, int n_in,
                              void* d_out, int out_size) {
    (void)in_sizes; (void)n_in; (void)out_size;
    const float* x  = (const float*)d_in[0];
    const float* om = (const float*)d_in[1];
    float* out = (float*)d_out;

    cudaFuncSetAttribute((const void*)fft_s1,
                         cudaFuncAttributeMaxDynamicSharedMemorySize, F_SMEM);
    cudaFuncSetAttribute((const void*)fft_s2,
                         cudaFuncAttributeMaxDynamicSharedMemorySize, F_SMEM);

    // Twiddle tables + barrier-state reset (once per launch).
    tw_init<<<1, 1024>>>();

    // FFT(x): x -> bufB (S1), bufB -> bufA (S2)
    fft_s1<<<dim3(FBLK, 1), FTHR, F_SMEM>>>(x);
    fft_s2<<<dim3(FBLK, 1), FTHR, F_SMEM>>>(0, nullptr);

    // 49 lambda-free VMD iterations; writes conj(ifftshift(u_hat)) to bufB.
    vmd_loop<<<NBLK, NTHR>>>(om);

    // FFT of the 3 modes: bufB -> bufA (S1), bufA -> out real (S2)
    fft_s1<<<dim3(FBLK, 3), FTHR, F_SMEM>>>(nullptr);
    fft_s2<<<dim3(FBLK, 3), FTHR, F_SMEM>>>(1, out);
}